// round 1
// baseline (speedup 1.0000x reference)
#include <cuda_runtime.h>
#include <cuda_bf16.h>
#include <math.h>

// ---------------- problem constants ----------------
#define NN      65536
#define CH      256      // IN_CH == GNN_DIM
#define GG      64       // groups
#define NPG     1024
#define KEIG    32
#define NB      64
#define BD      4
#define NBP     384
#define LAYERS  2

// ---------------- scratch (device globals; no mallocs allowed) -------------
__device__ float g_h  [NN * CH];        // 64 MB
__device__ float g_tmp[NN * CH];        // 64 MB
__device__ float g_agg[NN * CH];        // 64 MB
__device__ float g_rep[NN * NBP];       // 96 MB
__device__ float g_Q  [(size_t)NN * NB * 16]; // 268 MB
__device__ float g_hv [NN * CH];        // 64 MB
__device__ float g_hs [GG * KEIG * CH]; //  2 MB

__device__ __forceinline__ float gelu_exact(float x) {
    return 0.5f * x * (1.0f + erff(x * 0.7071067811865476f));
}

// ---------------- zero fill ----------------
__global__ void zero_kernel(float4* p, int n4) {
    int i = blockIdx.x * blockDim.x + threadIdx.x;
    if (i < n4) p[i] = make_float4(0.f, 0.f, 0.f, 0.f);
}

// ---------------- edge scatter: agg[dst] += h[src] ----------------
__global__ void scatter_kernel(const float* __restrict__ h,
                               const int* __restrict__ ei,
                               float* __restrict__ agg, int E) {
    long t = (long)blockIdx.x * blockDim.x + threadIdx.x;
    if (t >= (long)E * 64) return;
    int e = (int)(t >> 6);
    int q = (int)(t & 63);
    int s = ei[e];
    int d = ei[E + e];
    float4 v = ((const float4*)(h + (size_t)s * CH))[q];
    float* dst = agg + (size_t)d * CH + q * 4;
    atomicAdd(dst + 0, v.x);
    atomicAdd(dst + 1, v.y);
    atomicAdd(dst + 2, v.z);
    atomicAdd(dst + 3, v.w);
}

// ---------------- tiled SGEMM: C = epi(A[MxK] @ B[KxN] + bias) -------------
// EPI 0: C = acc + bias
// EPI 1: C = gelu(acc + bias)
// EPI 2: C = gelu(acc + bias + extra) + resid         (layer update, fused)
#define BM 64
#define BN 64
#define BK 16

template <int EPI>
__global__ void sgemm_k(const float* __restrict__ A, const float* __restrict__ B,
                        const float* __restrict__ bias,
                        const float* __restrict__ extra,
                        const float* __restrict__ resid,
                        float* __restrict__ C, int M, int Nn, int K) {
    __shared__ float As[BK][BM];
    __shared__ float Bs[BK][BN];

    const int tid = threadIdx.x;
    const int tx = tid & 15;      // col group
    const int ty = tid >> 4;      // row group
    const int rowBase = blockIdx.y * BM;
    const int colBase = blockIdx.x * BN;

    const int aRow = tid >> 2;
    const int aC4  = (tid & 3) * 4;
    const int bRow = tid >> 4;
    const int bC4  = (tid & 15) * 4;

    float acc[4][4];
#pragma unroll
    for (int i = 0; i < 4; i++)
#pragma unroll
        for (int j = 0; j < 4; j++) acc[i][j] = 0.f;

    for (int k0 = 0; k0 < K; k0 += BK) {
        float4 a = *(const float4*)&A[(size_t)(rowBase + aRow) * K + k0 + aC4];
        As[aC4 + 0][aRow] = a.x;
        As[aC4 + 1][aRow] = a.y;
        As[aC4 + 2][aRow] = a.z;
        As[aC4 + 3][aRow] = a.w;
        float4 b = *(const float4*)&B[(size_t)(k0 + bRow) * Nn + colBase + bC4];
        *(float4*)&Bs[bRow][bC4] = b;
        __syncthreads();
#pragma unroll
        for (int k = 0; k < BK; k++) {
            float4 av = *(const float4*)&As[k][ty * 4];
            float4 bv = *(const float4*)&Bs[k][tx * 4];
            float ar[4] = {av.x, av.y, av.z, av.w};
            float br[4] = {bv.x, bv.y, bv.z, bv.w};
#pragma unroll
            for (int i = 0; i < 4; i++)
#pragma unroll
                for (int j = 0; j < 4; j++) acc[i][j] += ar[i] * br[j];
        }
        __syncthreads();
    }

#pragma unroll
    for (int i = 0; i < 4; i++) {
        int row = rowBase + ty * 4 + i;
        float4 out4;
        float* o = &out4.x;
#pragma unroll
        for (int j = 0; j < 4; j++) {
            int col = colBase + tx * 4 + j;
            float v = acc[i][j] + bias[col];
            if (EPI == 2) v += extra[(size_t)row * Nn + col];
            if (EPI >= 1) v = gelu_exact(v);
            if (EPI == 2) v += resid[(size_t)row * Nn + col];
            o[j] = v;
        }
        *(float4*)&C[(size_t)row * Nn + colBase + tx * 4] = out4;
    }
}

// ---------------- Householder Q build + forward bundle rotate --------------
// One thread per (node n, bundle b). Q stored for reuse in final Q^T apply.
__global__ void hh_kernel(const float* __restrict__ rep, const float* __restrict__ x,
                          float* __restrict__ Qbuf, float* __restrict__ hv) {
    int t = blockIdx.x * blockDim.x + threadIdx.x;
    if (t >= NN * NB) return;
    int n = t >> 6;
    int b = t & 63;
    const float* p = rep + (size_t)n * NBP + b * 6;
    float p0 = p[0], p1 = p[1], p2 = p[2], p3 = p[3], p4 = p[4], p5 = p[5];

    float Q[4][4];
#pragma unroll
    for (int i = 0; i < 4; i++)
#pragma unroll
        for (int j = 0; j < 4; j++) Q[i][j] = (i == j) ? 1.f : 0.f;

    // reflector 0: v = (1, p0, p1, p2)
    {
        float inv = 2.f / (1.f + p0 * p0 + p1 * p1 + p2 * p2);
#pragma unroll
        for (int i = 0; i < 4; i++) {
            float qv = Q[i][0] + Q[i][1] * p0 + Q[i][2] * p1 + Q[i][3] * p2;
            float s = inv * qv;
            Q[i][0] -= s;
            Q[i][1] -= s * p0;
            Q[i][2] -= s * p1;
            Q[i][3] -= s * p2;
        }
    }
    // reflector 1: v = (0, 1, p3, p4)
    {
        float inv = 2.f / (1.f + p3 * p3 + p4 * p4);
#pragma unroll
        for (int i = 0; i < 4; i++) {
            float qv = Q[i][1] + Q[i][2] * p3 + Q[i][3] * p4;
            float s = inv * qv;
            Q[i][1] -= s;
            Q[i][2] -= s * p3;
            Q[i][3] -= s * p4;
        }
    }
    // reflector 2: v = (0, 0, 1, p5)
    {
        float inv = 2.f / (1.f + p5 * p5);
#pragma unroll
        for (int i = 0; i < 4; i++) {
            float qv = Q[i][2] + Q[i][3] * p5;
            float s = inv * qv;
            Q[i][2] -= s;
            Q[i][3] -= s * p5;
        }
    }

    float4 xv = *(const float4*)&x[(size_t)n * CH + b * 4];
    float xr[4] = {xv.x, xv.y, xv.z, xv.w};
    float4 ov;
    float* o = &ov.x;
#pragma unroll
    for (int c = 0; c < 4; c++)
        o[c] = Q[c][0] * xr[0] + Q[c][1] * xr[1] + Q[c][2] * xr[2] + Q[c][3] * xr[3];
    *(float4*)&hv[(size_t)n * CH + b * 4] = ov;

    float* qd = Qbuf + (size_t)t * 16;
#pragma unroll
    for (int i = 0; i < 4; i++)
        *(float4*)&qd[i * 4] = make_float4(Q[i][0], Q[i][1], Q[i][2], Q[i][3]);
}

// ---------------- spectral projection: hs[g] = diag-scale(ev^T @ hv) -------
__global__ void spec_fwd(const float* __restrict__ ev, const float* __restrict__ hv,
                         const float* __restrict__ eigval, const float* __restrict__ taus,
                         float* __restrict__ hs) {
    const int g = blockIdx.x;
    const int c = blockIdx.y * 128 + threadIdx.x;
    const int gbase = g * NPG;
    __shared__ float evs[8][KEIG];

    float acc[KEIG];
#pragma unroll
    for (int k = 0; k < KEIG; k++) acc[k] = 0.f;

    for (int n0 = 0; n0 < NPG; n0 += 8) {
        __syncthreads();
        for (int i = threadIdx.x; i < 8 * KEIG; i += 128) {
            int r = i >> 5, kk = i & 31;
            evs[r][kk] = ev[(size_t)(gbase + n0 + r) * KEIG + kk];
        }
        __syncthreads();
#pragma unroll
        for (int r = 0; r < 8; r++) {
            float hval = hv[(size_t)(gbase + n0 + r) * CH + c];
#pragma unroll
            for (int k = 0; k < KEIG; k++) acc[k] += evs[r][k] * hval;
        }
    }

    float tau = taus[c >> 2];
#pragma unroll
    for (int k = 0; k < KEIG; k++) {
        float f = expf(-eigval[g * KEIG + k] * tau);
        hs[(size_t)(g * KEIG + k) * CH + c] = acc[k] * f;
    }
}

// ---------------- spectral reprojection: h[g] = ev @ hs[g] ----------------
__global__ void spec_bwd(const float* __restrict__ ev, const float* __restrict__ hs,
                         float* __restrict__ out) {
    const int g = blockIdx.x;
    const int nbase = g * NPG + blockIdx.y * 64;
    __shared__ float hss[KEIG][CH];   // 32 KB
    __shared__ float evs[64][KEIG];   //  8 KB

    for (int i = 0; i < KEIG; i++)
        hss[i][threadIdx.x] = hs[(size_t)(g * KEIG + i) * CH + threadIdx.x];
    for (int i = threadIdx.x; i < 64 * KEIG; i += 256) {
        int r = i >> 5, kk = i & 31;
        evs[r][kk] = ev[(size_t)(nbase + r) * KEIG + kk];
    }
    __syncthreads();

    for (int r = 0; r < 64; r++) {
        float s = 0.f;
#pragma unroll
        for (int k = 0; k < KEIG; k++) s += evs[r][k] * hss[k][threadIdx.x];
        out[(size_t)(nbase + r) * CH + threadIdx.x] = s;
    }
}

// ---------------- final: out = Q^T @ hl per (n,b) ----------------
__global__ void final_kernel(const float* __restrict__ Qbuf,
                             const float* __restrict__ hl,
                             float* __restrict__ out) {
    int t = blockIdx.x * blockDim.x + threadIdx.x;
    if (t >= NN * NB) return;
    int n = t >> 6;
    int b = t & 63;
    const float* qd = Qbuf + (size_t)t * 16;
    float Q[4][4];
#pragma unroll
    for (int i = 0; i < 4; i++) {
        float4 q = *(const float4*)&qd[i * 4];
        Q[i][0] = q.x; Q[i][1] = q.y; Q[i][2] = q.z; Q[i][3] = q.w;
    }
    float4 hvv = *(const float4*)&hl[(size_t)n * CH + b * 4];
    float hr[4] = {hvv.x, hvv.y, hvv.z, hvv.w};
    float4 ov;
    float* o = &ov.x;
#pragma unroll
    for (int c = 0; c < 4; c++)
        o[c] = Q[0][c] * hr[0] + Q[1][c] * hr[1] + Q[2][c] * hr[2] + Q[3][c] * hr[3];
    *(float4*)&out[(size_t)n * CH + b * 4] = ov;
}

// ---------------- orchestration ----------------
extern "C" void kernel_launch(void* const* d_in, const int* in_sizes, int n_in,
                              void* d_out, int out_size) {
    const float* x      = (const float*)d_in[0];
    const float* eigvec = (const float*)d_in[1];
    const float* eigval = (const float*)d_in[2];
    const float* taus   = (const float*)d_in[3];
    const float* enc_w  = (const float*)d_in[4];
    const float* enc_b  = (const float*)d_in[5];
    const float* self_w = (const float*)d_in[6];
    const float* self_b = (const float*)d_in[7];
    const float* nb_w   = (const float*)d_in[8];
    const float* nb_b   = (const float*)d_in[9];
    const float* dec_w  = (const float*)d_in[10];
    const float* dec_b  = (const float*)d_in[11];
    const float* lin_w  = (const float*)d_in[12];
    const float* lin_b  = (const float*)d_in[13];
    const int*   ei     = (const int*)d_in[14];
    float* out = (float*)d_out;

    const int E = in_sizes[14] / 2;

    float *h, *tmp, *agg, *rep, *Qb, *hv, *hs;
    cudaGetSymbolAddress((void**)&h,   g_h);
    cudaGetSymbolAddress((void**)&tmp, g_tmp);
    cudaGetSymbolAddress((void**)&agg, g_agg);
    cudaGetSymbolAddress((void**)&rep, g_rep);
    cudaGetSymbolAddress((void**)&Qb,  g_Q);
    cudaGetSymbolAddress((void**)&hv,  g_hv);
    cudaGetSymbolAddress((void**)&hs,  g_hs);

    dim3 gemm_grid(CH / BN, NN / BM);
    dim3 dec_grid(NBP / BN, NN / BM);

    // 1. h = gelu(x @ enc_w + enc_b)
    sgemm_k<1><<<gemm_grid, 256>>>(x, enc_w, enc_b, nullptr, nullptr, h, NN, CH, CH);

    // 2. GNN layers
    for (int k = 0; k < LAYERS; k++) {
        zero_kernel<<<(NN * CH / 4 + 255) / 256, 256>>>((float4*)agg, NN * CH / 4);
        scatter_kernel<<<(int)(((long)E * 64 + 255) / 256), 256>>>(h, ei, agg, E);
        sgemm_k<0><<<gemm_grid, 256>>>(h, self_w + (size_t)k * CH * CH,
                                       self_b + k * CH, nullptr, nullptr, tmp, NN, CH, CH);
        // h = gelu(tmp + agg@nb_w + nb_b) + h   (elementwise-safe in-place)
        sgemm_k<2><<<gemm_grid, 256>>>(agg, nb_w + (size_t)k * CH * CH,
                                       nb_b + k * CH, tmp, h, h, NN, CH, CH);
    }

    // 3. node_rep = h @ dec_w + dec_b
    sgemm_k<0><<<dec_grid, 256>>>(h, dec_w, dec_b, nullptr, nullptr, rep, NN, NBP, CH);

    // 4. Householder Q + forward rotate of x
    hh_kernel<<<NN * NB / 256, 256>>>(rep, x, Qb, hv);

    // 5/6. spectral filter
    spec_fwd<<<dim3(GG, 2), 128>>>(eigvec, hv, eigval, taus, hs);
    spec_bwd<<<dim3(GG, NPG / 64), 256>>>(eigvec, hs, h);

    // 7. hl = h @ lin_w + lin_b
    sgemm_k<0><<<gemm_grid, 256>>>(h, lin_w, lin_b, nullptr, nullptr, tmp, NN, CH, CH);

    // 8. out = Q^T @ hl
    final_kernel<<<NN * NB / 256, 256>>>(Qb, tmp, out);
}

// round 2
// speedup vs baseline: 1.3435x; 1.3435x over previous
#include <cuda_runtime.h>
#include <cuda_bf16.h>
#include <math.h>

// ---------------- problem constants ----------------
#define NN      65536
#define CH      256      // IN_CH == GNN_DIM
#define GG      64
#define NPG     1024
#define KEIG    32
#define NB      64
#define BD      4
#define NBP     384
#define LAYERS  2

// ---------------- scratch (device globals; no mallocs allowed) -------------
__device__ float g_h  [NN * CH];
__device__ float g_tmp[NN * CH];
__device__ float g_agg[NN * CH];
__device__ float g_rep[NN * NBP];
__device__ float g_hv [NN * CH];
__device__ float g_hs [GG * KEIG * CH];

__device__ __forceinline__ float gelu_exact(float x) {
    return 0.5f * x * (1.0f + erff(x * 0.7071067811865476f));
}

// Householder Q from 6 params (BD=4, 3 reflectors)
__device__ __forceinline__ void build_Q(float p0, float p1, float p2, float p3,
                                        float p4, float p5, float Q[4][4]) {
#pragma unroll
    for (int i = 0; i < 4; i++)
#pragma unroll
        for (int j = 0; j < 4; j++) Q[i][j] = (i == j) ? 1.f : 0.f;
    {   // v = (1, p0, p1, p2)
        float inv = 2.f / (1.f + p0 * p0 + p1 * p1 + p2 * p2);
#pragma unroll
        for (int i = 0; i < 4; i++) {
            float qv = Q[i][0] + Q[i][1] * p0 + Q[i][2] * p1 + Q[i][3] * p2;
            float s = inv * qv;
            Q[i][0] -= s; Q[i][1] -= s * p0; Q[i][2] -= s * p1; Q[i][3] -= s * p2;
        }
    }
    {   // v = (0, 1, p3, p4)
        float inv = 2.f / (1.f + p3 * p3 + p4 * p4);
#pragma unroll
        for (int i = 0; i < 4; i++) {
            float qv = Q[i][1] + Q[i][2] * p3 + Q[i][3] * p4;
            float s = inv * qv;
            Q[i][1] -= s; Q[i][2] -= s * p3; Q[i][3] -= s * p4;
        }
    }
    {   // v = (0, 0, 1, p5)
        float inv = 2.f / (1.f + p5 * p5);
#pragma unroll
        for (int i = 0; i < 4; i++) {
            float qv = Q[i][2] + Q[i][3] * p5;
            float s = inv * qv;
            Q[i][2] -= s; Q[i][3] -= s * p5;
        }
    }
}

// ---------------- edge scatter: agg[dst] += h[src] (vector red atomics) ----
__global__ void scatter_kernel(const float* __restrict__ h,
                               const int* __restrict__ ei,
                               float* __restrict__ agg, int E) {
    long t = (long)blockIdx.x * blockDim.x + threadIdx.x;
    if (t >= (long)E * 64) return;
    int e = (int)(t >> 6);
    int q = (int)(t & 63);
    int s = ei[e];
    int d = ei[E + e];
    float4 v = ((const float4*)(h + (size_t)s * CH))[q];
    float* dst = agg + (size_t)d * CH + q * 4;
#if __CUDA_ARCH__ >= 900
    asm volatile("red.global.add.v4.f32 [%0], {%1, %2, %3, %4};"
                 :: "l"(dst), "f"(v.x), "f"(v.y), "f"(v.z), "f"(v.w)
                 : "memory");
#else
    atomicAdd(dst + 0, v.x);
    atomicAdd(dst + 1, v.y);
    atomicAdd(dst + 2, v.z);
    atomicAdd(dst + 3, v.w);
#endif
}

// ---------------- tiled SGEMM: 128x128x16, 8x8 microtile, double-buffered --
// EPI 0: C = acc + bias
// EPI 1: C = gelu(acc + bias)
// EPI 2: C = gelu(acc + bias + extra) + resid
#define BM 128
#define BN 128
#define BK 16

template <int EPI>
__global__ __launch_bounds__(256, 2)
void sgemm_k(const float* __restrict__ A, const float* __restrict__ B,
             const float* __restrict__ bias,
             const float* __restrict__ extra,
             const float* __restrict__ resid,
             float* __restrict__ C, int M, int Nn, int K) {
    __shared__ float As[2][BK][BM + 4];   // +4 pad for STS banking / alignment
    __shared__ float Bs[2][BK][BN];

    const int tid = threadIdx.x;
    const int rowBase = blockIdx.y * BM;
    const int colBase = blockIdx.x * BN;

    // A gmem load: k = tid&15 (coalesced along K), rows (tid>>4)+16*i
    const int aK = tid & 15;
    const int aR = tid >> 4;
    // B gmem load: row = tid>>5 (+8*i), col4 = (tid&31)*4
    const int bR = tid >> 5;
    const int bC = (tid & 31) * 4;

    const int tx = tid & 15;
    const int ty = tid >> 4;

    const float* Aptr = A + (size_t)(rowBase + aR) * K + aK;
    const float* Bptr = B + (size_t)bR * Nn + colBase + bC;

    float ra[8];
    float rb[8];

    // prefetch tile 0
#pragma unroll
    for (int i = 0; i < 8; i++) ra[i] = Aptr[(size_t)i * 16 * K];
#pragma unroll
    for (int i = 0; i < 2; i++)
        *(float4*)&rb[i * 4] = *(const float4*)&Bptr[(size_t)i * 8 * Nn];

#pragma unroll
    for (int i = 0; i < 8; i++) As[0][aK][aR + 16 * i] = ra[i];
#pragma unroll
    for (int i = 0; i < 2; i++)
        *(float4*)&Bs[0][bR + 8 * i][bC] = *(float4*)&rb[i * 4];
    __syncthreads();

    float acc[8][8];
#pragma unroll
    for (int i = 0; i < 8; i++)
#pragma unroll
        for (int j = 0; j < 8; j++) acc[i][j] = 0.f;

    const int ntiles = K / BK;
    int buf = 0;
    for (int kt = 0; kt < ntiles; kt++) {
        if (kt + 1 < ntiles) {
            const float* Ap = Aptr + (kt + 1) * BK;
#pragma unroll
            for (int i = 0; i < 8; i++) ra[i] = Ap[(size_t)i * 16 * K];
            const float* Bp = Bptr + (size_t)(kt + 1) * BK * Nn;
#pragma unroll
            for (int i = 0; i < 2; i++)
                *(float4*)&rb[i * 4] = *(const float4*)&Bp[(size_t)i * 8 * Nn];
        }
#pragma unroll
        for (int k = 0; k < BK; k++) {
            float a[8], b[8];
            *(float4*)&a[0] = *(const float4*)&As[buf][k][ty * 4];
            *(float4*)&a[4] = *(const float4*)&As[buf][k][64 + ty * 4];
            *(float4*)&b[0] = *(const float4*)&Bs[buf][k][tx * 4];
            *(float4*)&b[4] = *(const float4*)&Bs[buf][k][64 + tx * 4];
#pragma unroll
            for (int i = 0; i < 8; i++)
#pragma unroll
                for (int j = 0; j < 8; j++) acc[i][j] += a[i] * b[j];
        }
        if (kt + 1 < ntiles) {
            int nb = buf ^ 1;
#pragma unroll
            for (int i = 0; i < 8; i++) As[nb][aK][aR + 16 * i] = ra[i];
#pragma unroll
            for (int i = 0; i < 2; i++)
                *(float4*)&Bs[nb][bR + 8 * i][bC] = *(float4*)&rb[i * 4];
            __syncthreads();
            buf = nb;
        }
    }

    // epilogue
#pragma unroll
    for (int i = 0; i < 8; i++) {
        int rloc = (i < 4) ? (ty * 4 + i) : (64 + ty * 4 + (i - 4));
        int row = rowBase + rloc;
#pragma unroll
        for (int jh = 0; jh < 2; jh++) {
            float4 out4;
            float* o = &out4.x;
#pragma unroll
            for (int j2 = 0; j2 < 4; j2++) {
                int cloc = jh * 64 + tx * 4 + j2;
                int col = colBase + cloc;
                float v = acc[i][jh * 4 + j2] + bias[col];
                if (EPI == 2) v += extra[(size_t)row * Nn + col];
                if (EPI >= 1) v = gelu_exact(v);
                if (EPI == 2) v += resid[(size_t)row * Nn + col];
                o[j2] = v;
            }
            *(float4*)&C[(size_t)row * Nn + colBase + jh * 64 + tx * 4] = out4;
        }
    }
}

// ---------------- Householder Q + forward bundle rotate (Q not stored) -----
__global__ void hh_kernel(const float* __restrict__ rep, const float* __restrict__ x,
                          float* __restrict__ hv) {
    int t = blockIdx.x * blockDim.x + threadIdx.x;
    if (t >= NN * NB) return;
    int n = t >> 6;
    int b = t & 63;
    const float* p = rep + (size_t)n * NBP + b * 6;
    float Q[4][4];
    build_Q(p[0], p[1], p[2], p[3], p[4], p[5], Q);

    float4 xv = *(const float4*)&x[(size_t)n * CH + b * 4];
    float xr[4] = {xv.x, xv.y, xv.z, xv.w};
    float4 ov;
    float* o = &ov.x;
#pragma unroll
    for (int c = 0; c < 4; c++)
        o[c] = Q[c][0] * xr[0] + Q[c][1] * xr[1] + Q[c][2] * xr[2] + Q[c][3] * xr[3];
    *(float4*)&hv[(size_t)n * CH + b * 4] = ov;
}

// ---------------- spectral projection: hs[g] = diag-scale(ev^T @ hv) -------
__global__ void spec_fwd(const float* __restrict__ ev, const float* __restrict__ hv,
                         const float* __restrict__ eigval, const float* __restrict__ taus,
                         float* __restrict__ hs) {
    const int g = blockIdx.x;
    const int c = blockIdx.y * 128 + threadIdx.x;
    const int gbase = g * NPG;
    __shared__ float evs[8][KEIG];

    float acc[KEIG];
#pragma unroll
    for (int k = 0; k < KEIG; k++) acc[k] = 0.f;

    for (int n0 = 0; n0 < NPG; n0 += 8) {
        __syncthreads();
        for (int i = threadIdx.x; i < 8 * KEIG; i += 128) {
            int r = i >> 5, kk = i & 31;
            evs[r][kk] = ev[(size_t)(gbase + n0 + r) * KEIG + kk];
        }
        __syncthreads();
#pragma unroll
        for (int r = 0; r < 8; r++) {
            float hval = hv[(size_t)(gbase + n0 + r) * CH + c];
#pragma unroll
            for (int k = 0; k < KEIG; k++) acc[k] += evs[r][k] * hval;
        }
    }

    float tau = taus[c >> 2];
#pragma unroll
    for (int k = 0; k < KEIG; k++) {
        float f = expf(-eigval[g * KEIG + k] * tau);
        hs[(size_t)(g * KEIG + k) * CH + c] = acc[k] * f;
    }
}

// ---------------- spectral reprojection: h[g] = ev @ hs[g] ----------------
__global__ void spec_bwd(const float* __restrict__ ev, const float* __restrict__ hs,
                         float* __restrict__ out) {
    const int g = blockIdx.x;
    const int nbase = g * NPG + blockIdx.y * 64;
    __shared__ float hss[KEIG][CH];
    __shared__ float evs[64][KEIG];

    for (int i = 0; i < KEIG; i++)
        hss[i][threadIdx.x] = hs[(size_t)(g * KEIG + i) * CH + threadIdx.x];
    for (int i = threadIdx.x; i < 64 * KEIG; i += 256) {
        int r = i >> 5, kk = i & 31;
        evs[r][kk] = ev[(size_t)(nbase + r) * KEIG + kk];
    }
    __syncthreads();

    for (int r = 0; r < 64; r++) {
        float s = 0.f;
#pragma unroll
        for (int k = 0; k < KEIG; k++) s += evs[r][k] * hss[k][threadIdx.x];
        out[(size_t)(nbase + r) * CH + threadIdx.x] = s;
    }
}

// ---------------- final: out = Q^T @ hl per (n,b), Q recomputed ------------
__global__ void final_kernel(const float* __restrict__ rep,
                             const float* __restrict__ hl,
                             float* __restrict__ out) {
    int t = blockIdx.x * blockDim.x + threadIdx.x;
    if (t >= NN * NB) return;
    int n = t >> 6;
    int b = t & 63;
    const float* p = rep + (size_t)n * NBP + b * 6;
    float Q[4][4];
    build_Q(p[0], p[1], p[2], p[3], p[4], p[5], Q);

    float4 hvv = *(const float4*)&hl[(size_t)n * CH + b * 4];
    float hr[4] = {hvv.x, hvv.y, hvv.z, hvv.w};
    float4 ov;
    float* o = &ov.x;
#pragma unroll
    for (int c = 0; c < 4; c++)
        o[c] = Q[0][c] * hr[0] + Q[1][c] * hr[1] + Q[2][c] * hr[2] + Q[3][c] * hr[3];
    *(float4*)&out[(size_t)n * CH + b * 4] = ov;
}

// ---------------- orchestration ----------------
extern "C" void kernel_launch(void* const* d_in, const int* in_sizes, int n_in,
                              void* d_out, int out_size) {
    const float* x      = (const float*)d_in[0];
    const float* eigvec = (const float*)d_in[1];
    const float* eigval = (const float*)d_in[2];
    const float* taus   = (const float*)d_in[3];
    const float* enc_w  = (const float*)d_in[4];
    const float* enc_b  = (const float*)d_in[5];
    const float* self_w = (const float*)d_in[6];
    const float* self_b = (const float*)d_in[7];
    const float* nb_w   = (const float*)d_in[8];
    const float* nb_b   = (const float*)d_in[9];
    const float* dec_w  = (const float*)d_in[10];
    const float* dec_b  = (const float*)d_in[11];
    const float* lin_w  = (const float*)d_in[12];
    const float* lin_b  = (const float*)d_in[13];
    const int*   ei     = (const int*)d_in[14];
    float* out = (float*)d_out;

    const int E = in_sizes[14] / 2;

    float *h, *tmp, *agg, *rep, *hv, *hs;
    cudaGetSymbolAddress((void**)&h,   g_h);
    cudaGetSymbolAddress((void**)&tmp, g_tmp);
    cudaGetSymbolAddress((void**)&agg, g_agg);
    cudaGetSymbolAddress((void**)&rep, g_rep);
    cudaGetSymbolAddress((void**)&hv,  g_hv);
    cudaGetSymbolAddress((void**)&hs,  g_hs);

    dim3 gemm_grid(CH / BN, NN / BM);   // (2, 512)
    dim3 dec_grid(NBP / BN, NN / BM);   // (3, 512)

    // 1. h = gelu(x @ enc_w + enc_b)
    sgemm_k<1><<<gemm_grid, 256>>>(x, enc_w, enc_b, nullptr, nullptr, h, NN, CH, CH);

    // 2. GNN layers
    for (int k = 0; k < LAYERS; k++) {
        cudaMemsetAsync(agg, 0, (size_t)NN * CH * sizeof(float));
        scatter_kernel<<<(int)(((long)E * 64 + 255) / 256), 256>>>(h, ei, agg, E);
        sgemm_k<0><<<gemm_grid, 256>>>(h, self_w + (size_t)k * CH * CH,
                                       self_b + k * CH, nullptr, nullptr, tmp, NN, CH, CH);
        // h = gelu(tmp + agg@nb_w + nb_b) + h
        sgemm_k<2><<<gemm_grid, 256>>>(agg, nb_w + (size_t)k * CH * CH,
                                       nb_b + k * CH, tmp, h, h, NN, CH, CH);
    }

    // 3. node_rep = h @ dec_w + dec_b
    sgemm_k<0><<<dec_grid, 256>>>(h, dec_w, dec_b, nullptr, nullptr, rep, NN, NBP, CH);

    // 4. Householder Q + forward rotate of x
    hh_kernel<<<NN * NB / 256, 256>>>(rep, x, hv);

    // 5/6. spectral filter
    spec_fwd<<<dim3(GG, 2), 128>>>(eigvec, hv, eigval, taus, hs);
    spec_bwd<<<dim3(GG, NPG / 64), 256>>>(eigvec, hs, h);

    // 7. hl = h @ lin_w + lin_b
    sgemm_k<0><<<gemm_grid, 256>>>(h, lin_w, lin_b, nullptr, nullptr, tmp, NN, CH, CH);

    // 8. out = Q^T @ hl
    final_kernel<<<NN * NB / 256, 256>>>(rep, tmp, out);
}

// round 4
// speedup vs baseline: 1.9979x; 1.4871x over previous
#include <cuda_runtime.h>
#include <cuda_bf16.h>
#include <math.h>
#include <stdint.h>

// ---------------- problem constants ----------------
#define NN      65536
#define CH      256      // IN_CH == GNN_DIM
#define GG      64
#define NPG     1024
#define KEIG    32
#define NB      64
#define BD      4
#define NBP     384
#define LAYERS  2

#define WTOT    491520
#define OFF_ENC   0
#define OFF_SELF0 65536
#define OFF_SELF1 131072
#define OFF_NB0   196608
#define OFF_NB1   262144
#define OFF_DEC   327680
#define OFF_LIN   425984

// ---------------- scratch (device globals; no mallocs allowed) -------------
__device__ float g_h  [NN * CH];
__device__ float g_tmp[NN * CH];
__device__ float g_agg[NN * CH];
__device__ float g_rep[NN * NBP];
__device__ float g_hv [NN * CH];
__device__ float g_hs [GG * KEIG * CH];
__device__ __nv_bfloat16 g_whi[WTOT];
__device__ __nv_bfloat16 g_wlo[WTOT];

__device__ __forceinline__ float gelu_exact(float x) {
    return 0.5f * x * (1.0f + erff(x * 0.7071067811865476f));
}
__device__ __forceinline__ uint32_t pack_bf2(float a, float b) {
    __nv_bfloat162 t = __floats2bfloat162_rn(a, b);
    return *(uint32_t*)&t;
}
__device__ __forceinline__ uint32_t smem_u32(const void* p) {
    uint32_t a;
    asm("{ .reg .u64 t; cvta.to.shared.u64 t, %1; cvt.u32.u64 %0, t; }" : "=r"(a) : "l"(p));
    return a;
}
__device__ __forceinline__ void ldsm_x4(uint32_t* r, uint32_t addr) {
    asm volatile("ldmatrix.sync.aligned.m8n8.x4.shared.b16 {%0,%1,%2,%3}, [%4];"
                 : "=r"(r[0]), "=r"(r[1]), "=r"(r[2]), "=r"(r[3]) : "r"(addr));
}
__device__ __forceinline__ void mma_bf16(float* c, const uint32_t* a, uint32_t b0, uint32_t b1) {
    asm volatile("mma.sync.aligned.m16n8k16.row.col.f32.bf16.bf16.f32 "
                 "{%0,%1,%2,%3}, {%4,%5,%6,%7}, {%8,%9}, {%0,%1,%2,%3};"
                 : "+f"(c[0]), "+f"(c[1]), "+f"(c[2]), "+f"(c[3])
                 : "r"(a[0]), "r"(a[1]), "r"(a[2]), "r"(a[3]), "r"(b0), "r"(b1));
}

// ---------------- weight convert+transpose: W[K=256,N] -> Whi/Wlo[N,256] ---
__global__ void convert_w(const float* __restrict__ src,
                          __nv_bfloat16* __restrict__ dhi,
                          __nv_bfloat16* __restrict__ dlo, int Ncols) {
    int t = blockIdx.x * blockDim.x + threadIdx.x;
    if (t >= 256 * Ncols) return;
    int k = t / Ncols, n = t % Ncols;
    float v = src[t];
    __nv_bfloat16 h = __float2bfloat16_rn(v);
    dhi[(size_t)n * 256 + k] = h;
    dlo[(size_t)n * 256 + k] = __float2bfloat16_rn(v - __bfloat162float(h));
}

// ---------------- HMMA GEMM: C[M,Nn] = epi(A[M,256] @ W^T + bias) ----------
// CTA tile 128x64, warp tile 32x32 (warps 4x2), K chunks of 32.
// A fp32 -> bf16 hi/lo in load stage; W pre-converted [N][256] bf16 hi/lo.
// Split product: D = Ahi*Whi + Ahi*Wlo + Alo*Whi (fp32 accum).
#define PITCH 40   // bf16 elements per smem row (80 B) -> conflict-free ldmatrix

template <int EPI>
__global__ __launch_bounds__(256, 2)
void tgemm(const float* __restrict__ A,
           const __nv_bfloat16* __restrict__ Whi,
           const __nv_bfloat16* __restrict__ Wlo,
           const float* __restrict__ bias,
           const float* __restrict__ extra,
           const float* __restrict__ resid,
           float* __restrict__ C, int Nn) {
    __shared__ __align__(16) __nv_bfloat16 sAhi[128 * PITCH];
    __shared__ __align__(16) __nv_bfloat16 sAlo[128 * PITCH];
    __shared__ __align__(16) __nv_bfloat16 sBhi[64 * PITCH];
    __shared__ __align__(16) __nv_bfloat16 sBlo[64 * PITCH];

    const int tid  = threadIdx.x;
    const int lane = tid & 31;
    const int wid  = tid >> 5;
    const int warpM = wid & 3;    // 4 warps over M (32 rows each)
    const int warpN = wid >> 2;   // 2 warps over N (32 cols each)
    const int rowBase = blockIdx.y * 128;
    const int colBase = blockIdx.x * 64;

    const float* Ab = A + (size_t)rowBase * 256;
    const __nv_bfloat16* Wh = Whi + (size_t)colBase * 256;
    const __nv_bfloat16* Wl = Wlo + (size_t)colBase * 256;

    const uint32_t aHiB = smem_u32(sAhi);
    const uint32_t aLoB = smem_u32(sAlo);
    const uint32_t bHiB = smem_u32(sBhi);
    const uint32_t bLoB = smem_u32(sBlo);

    float c[2][4][4];
#pragma unroll
    for (int mi = 0; mi < 2; mi++)
#pragma unroll
        for (int ni = 0; ni < 4; ni++)
#pragma unroll
            for (int e = 0; e < 4; e++) c[mi][ni][e] = 0.f;

    // per-thread load coords
    const int aR = tid >> 3;          // + i*32 rows... (idx = i*256+tid; r = idx>>3)
    const int aKg = tid & 7;          // 4-float group
    const int bR = tid >> 2;          // 64 rows
    const int bKg = tid & 3;          // 8-bf16 group

    float4 pa[4];
    uint4  pbh, pbl;
    // prefetch chunk 0
#pragma unroll
    for (int i = 0; i < 4; i++)
        pa[i] = *(const float4*)&Ab[(size_t)(aR + i * 32) * 256 + aKg * 4];
    pbh = *(const uint4*)(Wh + (size_t)bR * 256 + bKg * 8);
    pbl = *(const uint4*)(Wl + (size_t)bR * 256 + bKg * 8);

    for (int kc = 0; kc < 8; kc++) {
        // ---- store prefetched chunk to smem (A converted to hi/lo) ----
#pragma unroll
        for (int i = 0; i < 4; i++) {
            int r = aR + i * 32;
            float4 v = pa[i];
            __nv_bfloat162 h01 = __floats2bfloat162_rn(v.x, v.y);
            __nv_bfloat162 h23 = __floats2bfloat162_rn(v.z, v.w);
            float l0 = v.x - __bfloat162float(h01.x);
            float l1 = v.y - __bfloat162float(h01.y);
            float l2 = v.z - __bfloat162float(h23.x);
            float l3 = v.w - __bfloat162float(h23.y);
            *(uint2*)((char*)sAhi + r * (PITCH * 2) + aKg * 8) =
                make_uint2(*(uint32_t*)&h01, *(uint32_t*)&h23);
            *(uint2*)((char*)sAlo + r * (PITCH * 2) + aKg * 8) =
                make_uint2(pack_bf2(l0, l1), pack_bf2(l2, l3));
        }
        *(uint4*)((char*)sBhi + bR * (PITCH * 2) + bKg * 16) = pbh;
        *(uint4*)((char*)sBlo + bR * (PITCH * 2) + bKg * 16) = pbl;
        __syncthreads();

        // ---- prefetch next chunk ----
        if (kc < 7) {
            const float* Ap = Ab + (kc + 1) * 32;
#pragma unroll
            for (int i = 0; i < 4; i++)
                pa[i] = *(const float4*)&Ap[(size_t)(aR + i * 32) * 256 + aKg * 4];
            const __nv_bfloat16* Whp = Wh + (kc + 1) * 32;
            const __nv_bfloat16* Wlp = Wl + (kc + 1) * 32;
            pbh = *(const uint4*)(Whp + (size_t)bR * 256 + bKg * 8);
            pbl = *(const uint4*)(Wlp + (size_t)bR * 256 + bKg * 8);
        }

        // ---- compute 2 k-steps of 16 ----
#pragma unroll
        for (int ks = 0; ks < 2; ks++) {
            uint32_t ah[2][4], al[2][4];
            const uint32_t aoff = (warpM * 32 + (lane & 15)) * (PITCH * 2)
                                  + ks * 32 + (lane >> 4) * 16;
#pragma unroll
            for (int mi = 0; mi < 2; mi++) {
                ldsm_x4(ah[mi], aHiB + aoff + mi * 16 * (PITCH * 2));
                ldsm_x4(al[mi], aLoB + aoff + mi * 16 * (PITCH * 2));
            }
            uint32_t bh[2][4], bl[2][4];
            const int g = lane >> 3, lr = lane & 7;
            const uint32_t boff = (warpN * 32 + ((g >> 1) << 3) + lr) * (PITCH * 2)
                                  + ks * 32 + (g & 1) * 16;
#pragma unroll
            for (int n2 = 0; n2 < 2; n2++) {
                ldsm_x4(bh[n2], bHiB + boff + n2 * 16 * (PITCH * 2));
                ldsm_x4(bl[n2], bLoB + boff + n2 * 16 * (PITCH * 2));
            }
#pragma unroll
            for (int mi = 0; mi < 2; mi++)
#pragma unroll
                for (int ni = 0; ni < 4; ni++) {
                    int n2 = ni >> 1, j = (ni & 1) * 2;
                    mma_bf16(c[mi][ni], ah[mi], bh[n2][j], bh[n2][j + 1]);
                    mma_bf16(c[mi][ni], ah[mi], bl[n2][j], bl[n2][j + 1]);
                    mma_bf16(c[mi][ni], al[mi], bh[n2][j], bh[n2][j + 1]);
                }
        }
        __syncthreads();
    }

    // ---- epilogue ----
#pragma unroll
    for (int mi = 0; mi < 2; mi++) {
        int row0 = rowBase + warpM * 32 + mi * 16 + (lane >> 2);
#pragma unroll
        for (int ni = 0; ni < 4; ni++) {
            int col = colBase + warpN * 32 + ni * 8 + (lane & 3) * 2;
            float b0 = bias[col], b1 = bias[col + 1];
#pragma unroll
            for (int half = 0; half < 2; half++) {
                int row = row0 + half * 8;
                float v0 = c[mi][ni][half * 2 + 0] + b0;
                float v1 = c[mi][ni][half * 2 + 1] + b1;
                if (EPI == 2) {
                    float2 ex = *(const float2*)&extra[(size_t)row * Nn + col];
                    v0 += ex.x; v1 += ex.y;
                }
                if (EPI >= 1) { v0 = gelu_exact(v0); v1 = gelu_exact(v1); }
                if (EPI == 2) {
                    float2 rs = *(const float2*)&resid[(size_t)row * Nn + col];
                    v0 += rs.x; v1 += rs.y;
                }
                *(float2*)&C[(size_t)row * Nn + col] = make_float2(v0, v1);
            }
        }
    }
}

// ---------------- Householder ----------------
__device__ __forceinline__ void build_Q(float p0, float p1, float p2, float p3,
                                        float p4, float p5, float Q[4][4]) {
#pragma unroll
    for (int i = 0; i < 4; i++)
#pragma unroll
        for (int j = 0; j < 4; j++) Q[i][j] = (i == j) ? 1.f : 0.f;
    {
        float inv = 2.f / (1.f + p0 * p0 + p1 * p1 + p2 * p2);
#pragma unroll
        for (int i = 0; i < 4; i++) {
            float qv = Q[i][0] + Q[i][1] * p0 + Q[i][2] * p1 + Q[i][3] * p2;
            float s = inv * qv;
            Q[i][0] -= s; Q[i][1] -= s * p0; Q[i][2] -= s * p1; Q[i][3] -= s * p2;
        }
    }
    {
        float inv = 2.f / (1.f + p3 * p3 + p4 * p4);
#pragma unroll
        for (int i = 0; i < 4; i++) {
            float qv = Q[i][1] + Q[i][2] * p3 + Q[i][3] * p4;
            float s = inv * qv;
            Q[i][1] -= s; Q[i][2] -= s * p3; Q[i][3] -= s * p4;
        }
    }
    {
        float inv = 2.f / (1.f + p5 * p5);
#pragma unroll
        for (int i = 0; i < 4; i++) {
            float qv = Q[i][2] + Q[i][3] * p5;
            float s = inv * qv;
            Q[i][2] -= s; Q[i][3] -= s * p5;
        }
    }
}

// ---------------- edge scatter: agg[dst] += h[src] ----------------
__global__ void scatter_kernel(const float* __restrict__ h,
                               const int* __restrict__ ei,
                               float* __restrict__ agg, int E) {
    long t = (long)blockIdx.x * blockDim.x + threadIdx.x;
    if (t >= (long)E * 64) return;
    int e = (int)(t >> 6);
    int q = (int)(t & 63);
    int s = ei[e];
    int d = ei[E + e];
    float4 v = ((const float4*)(h + (size_t)s * CH))[q];
    float* dst = agg + (size_t)d * CH + q * 4;
    asm volatile("red.global.add.v4.f32 [%0], {%1, %2, %3, %4};"
                 :: "l"(dst), "f"(v.x), "f"(v.y), "f"(v.z), "f"(v.w)
                 : "memory");
}

// ---------------- Householder Q + forward bundle rotate --------------------
__global__ void hh_kernel(const float* __restrict__ rep, const float* __restrict__ x,
                          float* __restrict__ hv) {
    int t = blockIdx.x * blockDim.x + threadIdx.x;
    if (t >= NN * NB) return;
    int n = t >> 6;
    int b = t & 63;
    const float* p = rep + (size_t)n * NBP + b * 6;
    float Q[4][4];
    build_Q(p[0], p[1], p[2], p[3], p[4], p[5], Q);
    float4 xv = *(const float4*)&x[(size_t)n * CH + b * 4];
    float xr[4] = {xv.x, xv.y, xv.z, xv.w};
    float4 ov; float* o = &ov.x;
#pragma unroll
    for (int cc = 0; cc < 4; cc++)
        o[cc] = Q[cc][0] * xr[0] + Q[cc][1] * xr[1] + Q[cc][2] * xr[2] + Q[cc][3] * xr[3];
    *(float4*)&hv[(size_t)n * CH + b * 4] = ov;
}

// ---------------- spectral projection ----------------
__global__ void spec_fwd(const float* __restrict__ ev, const float* __restrict__ hv,
                         const float* __restrict__ eigval, const float* __restrict__ taus,
                         float* __restrict__ hs) {
    const int g = blockIdx.x;
    const int cc = blockIdx.y * 128 + threadIdx.x;
    const int gbase = g * NPG;
    __shared__ float evs[8][KEIG];
    float acc[KEIG];
#pragma unroll
    for (int k = 0; k < KEIG; k++) acc[k] = 0.f;
    for (int n0 = 0; n0 < NPG; n0 += 8) {
        __syncthreads();
        for (int i = threadIdx.x; i < 8 * KEIG; i += 128) {
            int r = i >> 5, kk = i & 31;
            evs[r][kk] = ev[(size_t)(gbase + n0 + r) * KEIG + kk];
        }
        __syncthreads();
#pragma unroll
        for (int r = 0; r < 8; r++) {
            float hval = hv[(size_t)(gbase + n0 + r) * CH + cc];
#pragma unroll
            for (int k = 0; k < KEIG; k++) acc[k] += evs[r][k] * hval;
        }
    }
    float tau = taus[cc >> 2];
#pragma unroll
    for (int k = 0; k < KEIG; k++) {
        float f = expf(-eigval[g * KEIG + k] * tau);
        hs[(size_t)(g * KEIG + k) * CH + cc] = acc[k] * f;
    }
}

// ---------------- spectral reprojection ----------------
__global__ void spec_bwd(const float* __restrict__ ev, const float* __restrict__ hs,
                         float* __restrict__ out) {
    const int g = blockIdx.x;
    const int nbase = g * NPG + blockIdx.y * 64;
    __shared__ float hss[KEIG][CH];
    __shared__ float evs[64][KEIG];
    for (int i = 0; i < KEIG; i++)
        hss[i][threadIdx.x] = hs[(size_t)(g * KEIG + i) * CH + threadIdx.x];
    for (int i = threadIdx.x; i < 64 * KEIG; i += 256) {
        int r = i >> 5, kk = i & 31;
        evs[r][kk] = ev[(size_t)(nbase + r) * KEIG + kk];
    }
    __syncthreads();
    for (int r = 0; r < 64; r++) {
        float s = 0.f;
#pragma unroll
        for (int k = 0; k < KEIG; k++) s += evs[r][k] * hss[k][threadIdx.x];
        out[(size_t)(nbase + r) * CH + threadIdx.x] = s;
    }
}

// ---------------- final: out = Q^T @ hl ----------------
__global__ void final_kernel(const float* __restrict__ rep,
                             const float* __restrict__ hl,
                             float* __restrict__ out) {
    int t = blockIdx.x * blockDim.x + threadIdx.x;
    if (t >= NN * NB) return;
    int n = t >> 6;
    int b = t & 63;
    const float* p = rep + (size_t)n * NBP + b * 6;
    float Q[4][4];
    build_Q(p[0], p[1], p[2], p[3], p[4], p[5], Q);
    float4 hvv = *(const float4*)&hl[(size_t)n * CH + b * 4];
    float hr[4] = {hvv.x, hvv.y, hvv.z, hvv.w};
    float4 ov; float* o = &ov.x;
#pragma unroll
    for (int cc = 0; cc < 4; cc++)
        o[cc] = Q[0][cc] * hr[0] + Q[1][cc] * hr[1] + Q[2][cc] * hr[2] + Q[3][cc] * hr[3];
    *(float4*)&out[(size_t)n * CH + b * 4] = ov;
}

// ---------------- orchestration ----------------
extern "C" void kernel_launch(void* const* d_in, const int* in_sizes, int n_in,
                              void* d_out, int out_size) {
    const float* x      = (const float*)d_in[0];
    const float* eigvec = (const float*)d_in[1];
    const float* eigval = (const float*)d_in[2];
    const float* taus   = (const float*)d_in[3];
    const float* enc_w  = (const float*)d_in[4];
    const float* enc_b  = (const float*)d_in[5];
    const float* self_w = (const float*)d_in[6];
    const float* self_b = (const float*)d_in[7];
    const float* nb_w   = (const float*)d_in[8];
    const float* nb_b   = (const float*)d_in[9];
    const float* dec_w  = (const float*)d_in[10];
    const float* dec_b  = (const float*)d_in[11];
    const float* lin_w  = (const float*)d_in[12];
    const float* lin_b  = (const float*)d_in[13];
    const int*   ei     = (const int*)d_in[14];
    float* out = (float*)d_out;

    const int E = in_sizes[14] / 2;

    float *h, *tmp, *agg, *rep, *hv, *hs;
    __nv_bfloat16 *whi, *wlo;
    cudaGetSymbolAddress((void**)&h,   g_h);
    cudaGetSymbolAddress((void**)&tmp, g_tmp);
    cudaGetSymbolAddress((void**)&agg, g_agg);
    cudaGetSymbolAddress((void**)&rep, g_rep);
    cudaGetSymbolAddress((void**)&hv,  g_hv);
    cudaGetSymbolAddress((void**)&hs,  g_hs);
    cudaGetSymbolAddress((void**)&whi, g_whi);
    cudaGetSymbolAddress((void**)&wlo, g_wlo);

    // ---- convert + transpose weights to bf16 hi/lo [N][K] ----
    convert_w<<<(65536 + 255) / 256, 256>>>(enc_w, whi + OFF_ENC, wlo + OFF_ENC, 256);
    convert_w<<<(65536 + 255) / 256, 256>>>(self_w,          whi + OFF_SELF0, wlo + OFF_SELF0, 256);
    convert_w<<<(65536 + 255) / 256, 256>>>(self_w + 65536,  whi + OFF_SELF1, wlo + OFF_SELF1, 256);
    convert_w<<<(65536 + 255) / 256, 256>>>(nb_w,            whi + OFF_NB0,   wlo + OFF_NB0,   256);
    convert_w<<<(65536 + 255) / 256, 256>>>(nb_w + 65536,    whi + OFF_NB1,   wlo + OFF_NB1,   256);
    convert_w<<<(98304 + 255) / 256, 256>>>(dec_w, whi + OFF_DEC, wlo + OFF_DEC, 384);
    convert_w<<<(65536 + 255) / 256, 256>>>(lin_w, whi + OFF_LIN, wlo + OFF_LIN, 256);

    dim3 gemm_grid(CH / 64, NN / 128);   // (4, 512)
    dim3 dec_grid(NBP / 64, NN / 128);   // (6, 512)

    // 1. h = gelu(x @ enc_w + enc_b)
    tgemm<1><<<gemm_grid, 256>>>(x, whi + OFF_ENC, wlo + OFF_ENC, enc_b,
                                 nullptr, nullptr, h, CH);

    // 2. GNN layers
    const int woff_self[2] = {OFF_SELF0, OFF_SELF1};
    const int woff_nb[2]   = {OFF_NB0, OFF_NB1};
    for (int k = 0; k < LAYERS; k++) {
        cudaMemsetAsync(agg, 0, (size_t)NN * CH * sizeof(float));
        scatter_kernel<<<(int)(((long)E * 64 + 255) / 256), 256>>>(h, ei, agg, E);
        tgemm<0><<<gemm_grid, 256>>>(h, whi + woff_self[k], wlo + woff_self[k],
                                     self_b + k * CH, nullptr, nullptr, tmp, CH);
        // h = gelu(tmp + agg@nb_w + nb_b) + h
        tgemm<2><<<gemm_grid, 256>>>(agg, whi + woff_nb[k], wlo + woff_nb[k],
                                     nb_b + k * CH, tmp, h, h, CH);
    }

    // 3. node_rep = h @ dec_w + dec_b
    tgemm<0><<<dec_grid, 256>>>(h, whi + OFF_DEC, wlo + OFF_DEC, dec_b,
                                nullptr, nullptr, rep, NBP);

    // 4. Householder Q + forward rotate
    hh_kernel<<<NN * NB / 256, 256>>>(rep, x, hv);

    // 5/6. spectral filter
    spec_fwd<<<dim3(GG, 2), 128>>>(eigvec, hv, eigval, taus, hs);
    spec_bwd<<<dim3(GG, NPG / 64), 256>>>(eigvec, hs, h);

    // 7. hl = h @ lin_w + lin_b
    tgemm<0><<<gemm_grid, 256>>>(h, whi + OFF_LIN, wlo + OFF_LIN, lin_b,
                                 nullptr, nullptr, tmp, CH);

    // 8. out = Q^T @ hl
    final_kernel<<<NN * NB / 256, 256>>>(rep, tmp, out);
}